// round 16
// baseline (speedup 1.0000x reference)
#include <cuda_runtime.h>
#include <cuda_bf16.h>
#include <cstdint>

// ---------------------------------------------------------------------------
// GumbelVectorQuantizer on GB300, round 16:
//   gemm:     bf16 HMMA, KTILE=64 (12 iters, half the syncs), 2 CTAs/SM
//   epilogue: same-g warp mapping (pacc 20->10 regs) + next-pair logits
//             prefetch (software pipeline); redux.sync top-2 (R15 win)
//   fixup:    warp-per-pair exact ascending-k FMA resolve (unchanged)
// ---------------------------------------------------------------------------

#define BT     32768
#define DD     768
#define GK     640
#define KC     320
#define VDIM   128
#define NITER  12          // K iterations of 64
#define THETA  0.6f
#define GTH    17.1f       // 13.816 (g_max) + 2.627 (-g_min) + THETA
#define MAXFIX 65536

__device__ float g_logits[(size_t)BT * GK];                 // 83.9 MB
__device__ float g_prob[GK];
__device__ int   g_cnt[GK];
__device__ __align__(16) __nv_bfloat16 g_wth[(size_t)GK * DD];  // W^T bf16
__device__ __align__(16) float         g_wtf[(size_t)GK * DD];  // W^T fp32
__device__ int   g_fix_cnt;
__device__ int2  g_fix[MAXFIX];

// ---------------- exact-path log (FMA pipe, ~1 ulp; round-1 validated) --------
__device__ __forceinline__ float flog(float x) {
    int xi = __float_as_int(x);
    float e = (float)(((xi >> 23) & 0xFF) - 126);
    float m = __int_as_float((xi & 0x007FFFFF) | 0x3F000000);
    if (m < 0.70710678f) { m += m; e -= 1.0f; }
    float f = m - 1.0f;
    float z = f * f;
    float p = 7.0376836292E-2f;
    p = fmaf(p, f, -1.1514610310E-1f);
    p = fmaf(p, f,  1.1676998740E-1f);
    p = fmaf(p, f, -1.2420140846E-1f);
    p = fmaf(p, f,  1.4249322787E-1f);
    p = fmaf(p, f, -1.6668057665E-1f);
    p = fmaf(p, f,  2.0000714765E-1f);
    p = fmaf(p, f, -2.4999993993E-1f);
    p = fmaf(p, f,  3.3333331174E-1f);
    float y = p * f * z;
    y = fmaf(e, -2.12194440e-4f, y);
    y = fmaf(-0.5f, z, y);
    float r = f + y;
    r = fmaf(e, 0.693359375f, r);
    return r;
}

// MUFU gumbel, guarded near u->1
__device__ __forceinline__ float fgum(float un) {
    float u = fmaf(un, 0.999998f, 1e-6f);
    float nlu = -__logf(u);
    if (u > 0.99f) nlu = -flog(u);
    return -__logf(nlu);
}

// ---------------- order-preserving float<->uint map + warp redux ----------------
__device__ __forceinline__ uint32_t ordf(float f) {
    uint32_t u = __float_as_uint(f);
    return (u & 0x80000000u) ? ~u : (u | 0x80000000u);
}
__device__ __forceinline__ float unordf(uint32_t o) {
    uint32_t u = (o & 0x80000000u) ? (o ^ 0x80000000u) : ~o;
    return __uint_as_float(u);
}
__device__ __forceinline__ uint32_t redux_max(uint32_t v) {
    uint32_t r;
    asm("redux.sync.max.u32 %0, %1, 0xffffffff;" : "=r"(r) : "r"(v));
    return r;
}
__device__ __forceinline__ uint32_t redux_min(uint32_t v) {
    uint32_t r;
    asm("redux.sync.min.u32 %0, %1, 0xffffffff;" : "=r"(r) : "r"(v));
    return r;
}
__device__ __forceinline__ void warp_top2(float& M, float& M2, int& I) {
    const uint32_t mo  = ordf(M);
    const uint32_t Mo  = redux_max(mo);
    const uint32_t c2  = (mo == Mo) ? ordf(M2) : mo;
    const uint32_t M2o = redux_max(c2);
    const uint32_t ic  = (mo == Mo) ? (uint32_t)I : 0x7FFFFFFFu;
    I  = (int)redux_min(ic);
    M  = unordf(Mo);
    M2 = unordf(M2o);
}

// ---------------- PTX helpers --------------------------------------------------
__device__ __forceinline__ uint32_t smem_u32(const void* p) {
    uint32_t a;
    asm("{ .reg .u64 t; cvta.to.shared.u64 t, %1; cvt.u32.u64 %0, t; }"
        : "=r"(a) : "l"(p));
    return a;
}
#define LDMATRIX_X4(r0, r1, r2, r3, addr) \
    asm volatile("ldmatrix.sync.aligned.m8n8.x4.shared.b16 {%0,%1,%2,%3}, [%4];" \
                 : "=r"(r0), "=r"(r1), "=r"(r2), "=r"(r3) : "r"(addr))
#define MMA16816(d, a, b0, b1) \
    asm volatile("mma.sync.aligned.m16n8k16.row.col.f32.bf16.bf16.f32 " \
                 "{%0,%1,%2,%3}, {%4,%5,%6,%7}, {%8,%9}, {%0,%1,%2,%3};" \
                 : "+f"((d)[0]), "+f"((d)[1]), "+f"((d)[2]), "+f"((d)[3]) \
                 : "r"((a)[0]), "r"((a)[1]), "r"((a)[2]), "r"((a)[3]), \
                   "r"(b0), "r"(b1))
#define CP_ASYNC16(dst, src) \
    asm volatile("cp.async.cg.shared.global [%0], [%1], 16;" \
                 :: "r"(dst), "l"(src) : "memory")
#define CP_COMMIT() asm volatile("cp.async.commit_group;" ::: "memory")
#define CP_WAIT0()  asm volatile("cp.async.wait_group 0;" ::: "memory")

// smem: A[buf]: 64 rows x 144B = 9216; B[buf]: 320 rows x 144B = 46080
#define A_OFF(buf) ((buf) * 9216)
#define B_OFF(buf) (18432 + (buf) * 46080)
#define GEMM_SMEM 110592

__device__ __forceinline__ uint32_t pkbf(float a, float b) {
    return (uint32_t)__bfloat16_as_ushort(__float2bfloat16_rn(a)) |
           ((uint32_t)__bfloat16_as_ushort(__float2bfloat16_rn(b)) << 16);
}

// ---------------- zero ----------------------------------------------------------
__global__ void zero_kernel() {
    int t = blockIdx.x * blockDim.x + threadIdx.x;
    if (t < GK) { g_prob[t] = 0.0f; g_cnt[t] = 0; }
    if (t == GK) g_fix_cnt = 0;
}

// ---------------- W^T: bf16 + fp32, tiled transpose ------------------------------
__global__ __launch_bounds__(256)
void wsplit_kernel(const float* __restrict__ W) {
    __shared__ float tile[32][33];
    const int n0 = blockIdx.x * 32;
    const int k0 = blockIdx.y * 32;
    const int tx = threadIdx.x & 31;
    const int ty = threadIdx.x >> 5;
#pragma unroll
    for (int i = 0; i < 32; i += 8)
        tile[ty + i][tx] = W[(size_t)(k0 + ty + i) * GK + n0 + tx];
    __syncthreads();
#pragma unroll
    for (int i = 0; i < 32; i += 8) {
        const int n = n0 + ty + i, k = k0 + tx;
        float x = tile[tx][ty + i];
        g_wth[(size_t)n * DD + k] = __float2bfloat16_rn(x);
        g_wtf[(size_t)n * DD + k] = x;
    }
}

// ---------------- HMMA GEMM: KTILE=64, CTA tile 64x320, 2 CTAs/SM -----------------
__global__ __launch_bounds__(256, 2)
void gemm_hmma_kernel(const float* __restrict__ X, const float* __restrict__ bias) {
    extern __shared__ char sm[];
    const uint32_t smb = smem_u32(sm);
    const int tid  = threadIdx.x;
    const int lane = tid & 31;
    const int wid  = tid >> 5;
    const int wm   = wid & 1;
    const int wn   = wid >> 1;
    const int g    = blockIdx.x;
    const int bm   = blockIdx.y;

    float acc[2][10][4];
#pragma unroll
    for (int i = 0; i < 2; i++)
#pragma unroll
        for (int j = 0; j < 10; j++)
#pragma unroll
            for (int q = 0; q < 4; q++) acc[i][j][q] = 0.0f;

    const int a_row = tid >> 2;           // 0..63
    const int a_q   = tid & 3;            // 16-float chunk within 64
    const float* Xrow = X + (size_t)(bm * 64 + a_row) * DD + a_q * 16;

    // prologue: B tile 0 (2560 cp.asyncs) + A tile 0
    for (int idx = tid; idx < 2560; idx += 256) {
        int n = idx >> 3, c = idx & 7;
        CP_ASYNC16(smb + B_OFF(0) + n * 144 + c * 16,
                   &g_wth[(size_t)(g * KC + n) * DD + c * 8]);
    }
    CP_COMMIT();
    {
        float4 v0 = *(const float4*)(Xrow);
        float4 v1 = *(const float4*)(Xrow + 4);
        float4 v2 = *(const float4*)(Xrow + 8);
        float4 v3 = *(const float4*)(Xrow + 12);
        uint4 p0 = make_uint4(pkbf(v0.x, v0.y), pkbf(v0.z, v0.w),
                              pkbf(v1.x, v1.y), pkbf(v1.z, v1.w));
        uint4 p1 = make_uint4(pkbf(v2.x, v2.y), pkbf(v2.z, v2.w),
                              pkbf(v3.x, v3.y), pkbf(v3.z, v3.w));
        *(uint4*)(sm + A_OFF(0) + a_row * 144 + a_q * 32)      = p0;
        *(uint4*)(sm + A_OFF(0) + a_row * 144 + a_q * 32 + 16) = p1;
    }
    CP_WAIT0();
    __syncthreads();

    const int a_lrow = (lane & 15);
    const int a_lcol = (lane >> 4) * 16;
    const int b_lrow = (lane & 7) + ((lane >> 4) & 1) * 8;
    const int b_lcol = ((lane >> 3) & 1) * 16;
    const int b_nbase = (wn * 80 + b_lrow) * 144 + b_lcol;

    int buf = 0;
    for (int t = 0; t < NITER; t++) {
        float4 nv0, nv1, nv2, nv3;
        if (t + 1 < NITER) {
            const float* nx = Xrow + (t + 1) * 64;
            nv0 = *(const float4*)(nx);
            nv1 = *(const float4*)(nx + 4);
            nv2 = *(const float4*)(nx + 8);
            nv3 = *(const float4*)(nx + 12);
            const int k0 = (t + 1) * 64;
            for (int idx = tid; idx < 2560; idx += 256) {
                int n = idx >> 3, c = idx & 7;
                CP_ASYNC16(smb + B_OFF(buf ^ 1) + n * 144 + c * 16,
                           &g_wth[(size_t)(g * KC + n) * DD + k0 + c * 8]);
            }
            CP_COMMIT();
        }
#pragma unroll
        for (int kh = 0; kh < 4; kh++) {
            uint32_t ah[2][4];
#pragma unroll
            for (int mt = 0; mt < 2; mt++) {
                const int row = wm * 32 + mt * 16 + a_lrow;
                LDMATRIX_X4(ah[mt][0], ah[mt][1], ah[mt][2], ah[mt][3],
                            smb + A_OFF(buf) + row * 144 + kh * 32 + a_lcol);
            }
            uint32_t bb[2][4];
            LDMATRIX_X4(bb[0][0], bb[0][1], bb[0][2], bb[0][3],
                        smb + B_OFF(buf) + b_nbase + kh * 32);
#pragma unroll
            for (int bg = 0; bg < 5; bg++) {
                const int cur = bg & 1, nxt = cur ^ 1;
                if (bg < 4)
                    LDMATRIX_X4(bb[nxt][0], bb[nxt][1], bb[nxt][2], bb[nxt][3],
                                smb + B_OFF(buf) + b_nbase + (bg + 1) * 16 * 144 + kh * 32);
#pragma unroll
                for (int h2 = 0; h2 < 2; h2++) {
                    MMA16816(acc[0][bg * 2 + h2], ah[0], bb[cur][h2 * 2], bb[cur][h2 * 2 + 1]);
                    MMA16816(acc[1][bg * 2 + h2], ah[1], bb[cur][h2 * 2], bb[cur][h2 * 2 + 1]);
                }
            }
        }
        if (t + 1 < NITER) {
            uint4 p0 = make_uint4(pkbf(nv0.x, nv0.y), pkbf(nv0.z, nv0.w),
                                  pkbf(nv1.x, nv1.y), pkbf(nv1.z, nv1.w));
            uint4 p1 = make_uint4(pkbf(nv2.x, nv2.y), pkbf(nv2.z, nv2.w),
                                  pkbf(nv3.x, nv3.y), pkbf(nv3.z, nv3.w));
            *(uint4*)(sm + A_OFF(buf ^ 1) + a_row * 144 + a_q * 32)      = p0;
            *(uint4*)(sm + A_OFF(buf ^ 1) + a_row * 144 + a_q * 32 + 16) = p1;
            CP_WAIT0();
        }
        __syncthreads();
        buf ^= 1;
    }

#pragma unroll
    for (int nt = 0; nt < 10; nt++) {
        const int c = wn * 80 + nt * 8 + (lane & 3) * 2;
        const float b0 = bias[g * KC + c];
        const float b1 = bias[g * KC + c + 1];
#pragma unroll
        for (int mt = 0; mt < 2; mt++) {
            const int r0 = bm * 64 + wm * 32 + mt * 16 + (lane >> 2);
            float* p0 = g_logits + ((size_t)r0 * 2 + g) * KC + c;
            float* p1 = g_logits + ((size_t)(r0 + 8) * 2 + g) * KC + c;
            *(float2*)p0 = make_float2(acc[mt][nt][0] + b0, acc[mt][nt][1] + b1);
            *(float2*)p1 = make_float2(acc[mt][nt][2] + b0, acc[mt][nt][3] + b1);
        }
    }
}

// ---------------- fused epilogue (same-g warps + logits prefetch pipeline) ---------
__global__ __launch_bounds__(256)
void epilogue_kernel(const float* __restrict__ noise,
                     const float* __restrict__ cb,
                     float* __restrict__ out) {
    __shared__ float s_prob[GK];
    __shared__ int   s_cnt[GK];
    const int tid = threadIdx.x;
    for (int i = tid; i < GK; i += 256) { s_prob[i] = 0.0f; s_cnt[i] = 0; }
    __syncthreads();

    const int lane = tid & 31;
    const int warp = tid >> 5;
    const int wg   = blockIdx.x * 8 + warp;   // 0..4095
    const int g    = wg & 1;
    const int row0 = (wg >> 1) * 16;

    float pacc[10];
#pragma unroll
    for (int j = 0; j < 10; j++) pacc[j] = 0.0f;

    // prime the pipeline: logits of first pair
    float l[10];
    {
        const float* lr = g_logits + ((size_t)row0 * 2 + g) * KC;
#pragma unroll
        for (int j = 0; j < 10; j++) l[j] = lr[lane + 32 * j];
    }

    for (int pp = 0; pp < 16; pp++) {
        const int r = row0 + pp;
        const int pair = r * 2 + g;
        const float* nrow = noise + (size_t)pair * KC;

        float nv[10];
#pragma unroll
        for (int j = 0; j < 10; j++) nv[j] = nrow[lane + 32 * j];

        // prefetch next pair's logits (hidden under this pair's compute)
        float lN[10];
        if (pp < 15) {
            const float* lr = g_logits + (size_t)(pair + 2) * KC;
#pragma unroll
            for (int j = 0; j < 10; j++) lN[j] = lr[lane + 32 * j];
        }

        // hard top-2: local scan, then 3-op redux reduction
        float M = l[0], M2 = -3.4e38f; int I = lane;
#pragma unroll
        for (int j = 1; j < 10; j++) {
            if (l[j] > M) { M2 = M; M = l[j]; I = lane + 32 * j; }
            else if (l[j] > M2) M2 = l[j];
        }
        warp_top2(M, M2, I);

        // gumbel top-2: fgum only where the bound allows a win
        const float cut = M - GTH;
        float GM = -3.4e38f, GM2 = -3.4e38f; int GI = 0x7FFFFFFF;
#pragma unroll
        for (int j = 0; j < 10; j++) {
            if (l[j] > cut) {
                const float gl = l[j] + fgum(nv[j]);
                if (gl > GM)       { GM2 = GM; GM = gl; GI = lane + 32 * j; }
                else if (gl > GM2) { GM2 = gl; }
            }
        }
        warp_top2(GM, GM2, GI);

        // softmax accumulation (MUFU exp)
        float s = 0.0f;
        float e[10];
#pragma unroll
        for (int j = 0; j < 10; j++) { e[j] = __expf(l[j] - M); s += e[j]; }
#pragma unroll
        for (int off = 16; off; off >>= 1)
            s += __shfl_xor_sync(0xffffffffu, s, off);
        const float inv = 1.0f / s;
#pragma unroll
        for (int j = 0; j < 10; j++) pacc[j] += e[j] * inv;

        if (lane == 0) {
            atomicAdd(&s_cnt[g * KC + I], 1);
            if (M - M2 < THETA || GM - GM2 < THETA) {
                int pos = atomicAdd(&g_fix_cnt, 1);
                if (pos < MAXFIX) g_fix[pos] = make_int2(pair, I);
            }
        }

        const float4* src = (const float4*)(cb + ((size_t)(g * KC) + GI) * VDIM);
        float4*       dst = (float4*)(out + (size_t)r * 256 + g * VDIM);
        dst[lane] = src[lane];

        if (pp < 15) {
#pragma unroll
            for (int j = 0; j < 10; j++) l[j] = lN[j];
        }
    }

#pragma unroll
    for (int j = 0; j < 10; j++)
        atomicAdd(&s_prob[g * KC + lane + 32 * j], pacc[j]);

    __syncthreads();
    for (int i = tid; i < GK; i += 256) {
        atomicAdd(&g_prob[i], s_prob[i]);
        atomicAdd(&g_cnt[i],  s_cnt[i]);
    }
}

// ---------------- fixup: exact resolve of candidates (round-15 verbatim) ------------
__global__ __launch_bounds__(256)
void fixup_kernel(const float* __restrict__ X, const float* __restrict__ bias,
                  const float* __restrict__ noise, const float* __restrict__ cb,
                  float* __restrict__ out) {
    __shared__ int s_cols[8][32];
    __shared__ int s_n[8];
    const int lane = threadIdx.x & 31;
    const int w    = threadIdx.x >> 5;
    const int gw   = blockIdx.x * 8 + w;
    const int nwarps = gridDim.x * 8;
    const int total = min(g_fix_cnt, MAXFIX);

    for (int f = gw; f < total; f += nwarps) {
        const int2 rec = g_fix[f];
        const int pair = rec.x, Iapp = rec.y;
        const int r = pair >> 1, g = pair & 1;
        const float* lrow = g_logits + (size_t)pair * KC;
        const float* nrow = noise    + (size_t)pair * KC;

        float l[10], nv[10];
#pragma unroll
        for (int j = 0; j < 10; j++) {
            const int k = lane + 32 * j;
            l[j]  = lrow[k];
            nv[j] = nrow[k];
        }

        float M = l[0];
#pragma unroll
        for (int j = 1; j < 10; j++) M = fmaxf(M, l[j]);
        M = unordf(redux_max(ordf(M)));

        const float cut = M - GTH;
        float gl[10];
        float GM = -3.4e38f;
#pragma unroll
        for (int j = 0; j < 10; j++) {
            gl[j] = -3.4e38f;
            if (l[j] > cut) {
                float u = fmaf(nv[j], 0.999998f, 1e-6f);
                gl[j] = l[j] - flog(-flog(u));
                GM = fmaxf(GM, gl[j]);
            }
        }
        GM = unordf(redux_max(ordf(GM)));

        if (lane == 0) s_n[w] = 0;
        __syncwarp();
#pragma unroll
        for (int j = 0; j < 10; j++) {
            const int hardc = l[j]  > M  - THETA;
            const int gumc  = gl[j] > GM - THETA;
            if (hardc || gumc) {
                int p = atomicAdd(&s_n[w], 1);
                if (p < 32)
                    s_cols[w][p] = (lane + 32 * j) | (hardc << 16) | (gumc << 17);
            }
        }
        __syncwarp();
        const int cnt = min(s_n[w], 32);

        float le = -3.4e38f, ge = -3.4e38f;
        int ci = KC;
        if (lane < cnt) {
            const int ent = s_cols[w][lane];
            ci = ent & 0xFFFF;
            const float* xr = X + (size_t)r * DD;
            const float* wc = g_wtf + (size_t)(g * KC + ci) * DD;
            float acc = 0.0f;
            for (int k = 0; k < DD; k++)
                acc = fmaf(xr[k], wc[k], acc);       // ascending-k exact chain
            const float ex = acc + bias[g * KC + ci];
            float u = fmaf(nrow[ci], 0.999998f, 1e-6f);
            const float gum = -flog(-flog(u));
            if (ent & 0x10000) le = ex;
            if (ent & 0x20000) ge = ex + gum;
        }
        int hi = ci, gi = ci;
        float hv = le, gv = ge;
#pragma unroll
        for (int off = 16; off; off >>= 1) {
            float ov = __shfl_xor_sync(0xffffffffu, hv, off);
            int   oi = __shfl_xor_sync(0xffffffffu, hi, off);
            if (ov > hv || (ov == hv && oi < hi)) { hv = ov; hi = oi; }
            float o2 = __shfl_xor_sync(0xffffffffu, gv, off);
            int   i2 = __shfl_xor_sync(0xffffffffu, gi, off);
            if (o2 > gv || (o2 == gv && i2 < gi)) { gv = o2; gi = i2; }
        }

        if (lane == 0 && hi != Iapp) {
            atomicSub(&g_cnt[g * KC + Iapp], 1);
            atomicAdd(&g_cnt[g * KC + hi], 1);
        }
        const float4* src = (const float4*)(cb + ((size_t)(g * KC) + gi) * VDIM);
        float4*       dst = (float4*)(out + (size_t)r * 256 + g * VDIM);
        dst[lane] = src[lane];
        __syncwarp();
    }
}

// ---------------- perplexity scalars (parallel reduction) ---------------------------
__global__ void finalize_kernel(float* __restrict__ out, int scalar_base) {
    __shared__ float sh[GK], sp[GK];
    __shared__ float red[4];
    const int t = threadIdx.x;
    if (t < GK) {
        float hp = (float)g_cnt[t] * (1.0f / (float)BT);
        float ap = g_prob[t]       * (1.0f / (float)BT);
        sh[t] = hp * logf(hp + 1e-7f);
        sp[t] = ap * logf(ap + 1e-7f);
    }
    __syncthreads();
    if (t < 64) {
        const int gi = t >> 5, lane = t & 31;
        float a = 0.0f, b = 0.0f;
        for (int k = lane; k < KC; k += 32) {
            a += sh[gi * KC + k];
            b += sp[gi * KC + k];
        }
#pragma unroll
        for (int off = 16; off; off >>= 1) {
            a += __shfl_xor_sync(0xffffffffu, a, off);
            b += __shfl_xor_sync(0xffffffffu, b, off);
        }
        if (lane == 0) { red[gi] = a; red[2 + gi] = b; }
    }
    __syncthreads();
    if (t == 0) {
        out[scalar_base]     = expf(-red[0]) + expf(-red[1]);
        out[scalar_base + 1] = expf(-red[2]) + expf(-red[3]);
    }
}

// ---------------- launch --------------------------------------------------------------
extern "C" void kernel_launch(void* const* d_in, const int* in_sizes, int n_in,
                              void* d_out, int out_size) {
    const float* x     = (const float*)d_in[0];
    const float* W     = (const float*)d_in[1];
    const float* bias  = (const float*)d_in[2];
    const float* cb    = (const float*)d_in[3];
    const float* noise = (const float*)d_in[4];
    float* out = (float*)d_out;

    cudaFuncSetAttribute(gemm_hmma_kernel,
                         cudaFuncAttributeMaxDynamicSharedMemorySize, GEMM_SMEM);

    zero_kernel<<<3, 256>>>();
    dim3 wgrid(20, 24);
    wsplit_kernel<<<wgrid, 256>>>(W);
    dim3 grid(2, 512);
    gemm_hmma_kernel<<<grid, 256, GEMM_SMEM>>>(x, bias);
    epilogue_kernel<<<512, 256>>>(noise, cb, out);
    fixup_kernel<<<512, 256>>>(x, bias, noise, cb, out);
    finalize_kernel<<<1, GK>>>(out, out_size - 2);
}

// round 17
// speedup vs baseline: 1.1136x; 1.1136x over previous
#include <cuda_runtime.h>
#include <cuda_bf16.h>
#include <cstdint>

// ---------------------------------------------------------------------------
// GumbelVectorQuantizer on GB300, round 17 (R15 base + same-g warps + merged zero):
//   gemm:     bf16 HMMA, KTILE=32, 256-thr CTAs (64x320), 2 CTAs/SM  [R8/R15]
//   epilogue: grid 512, 16 same-group pairs/warp; redux.sync top-2   [R15 win]
//   fixup:    warp-per-pair exact ascending-k FMA resolve            [R15]
// ---------------------------------------------------------------------------

#define BT     32768
#define DD     768
#define GK     640
#define KC     320
#define VDIM   128
#define NITER  24
#define THETA  0.6f
#define GTH    17.1f      // 13.816 (g_max) + 2.627 (-g_min) + THETA
#define MAXFIX 65536

__device__ float g_logits[(size_t)BT * GK];                 // 83.9 MB
__device__ float g_prob[GK];
__device__ int   g_cnt[GK];
__device__ __align__(16) __nv_bfloat16 g_wth[(size_t)GK * DD];  // W^T bf16
__device__ __align__(16) float         g_wtf[(size_t)GK * DD];  // W^T fp32
__device__ int   g_fix_cnt;
__device__ int2  g_fix[MAXFIX];

// ---------------- exact-path log (FMA pipe, ~1 ulp; round-1 validated) --------
__device__ __forceinline__ float flog(float x) {
    int xi = __float_as_int(x);
    float e = (float)(((xi >> 23) & 0xFF) - 126);
    float m = __int_as_float((xi & 0x007FFFFF) | 0x3F000000);
    if (m < 0.70710678f) { m += m; e -= 1.0f; }
    float f = m - 1.0f;
    float z = f * f;
    float p = 7.0376836292E-2f;
    p = fmaf(p, f, -1.1514610310E-1f);
    p = fmaf(p, f,  1.1676998740E-1f);
    p = fmaf(p, f, -1.2420140846E-1f);
    p = fmaf(p, f,  1.4249322787E-1f);
    p = fmaf(p, f, -1.6668057665E-1f);
    p = fmaf(p, f,  2.0000714765E-1f);
    p = fmaf(p, f, -2.4999993993E-1f);
    p = fmaf(p, f,  3.3333331174E-1f);
    float y = p * f * z;
    y = fmaf(e, -2.12194440e-4f, y);
    y = fmaf(-0.5f, z, y);
    float r = f + y;
    r = fmaf(e, 0.693359375f, r);
    return r;
}

// MUFU gumbel, guarded near u->1
__device__ __forceinline__ float fgum(float un) {
    float u = fmaf(un, 0.999998f, 1e-6f);
    float nlu = -__logf(u);
    if (u > 0.99f) nlu = -flog(u);
    return -__logf(nlu);
}

// ---------------- order-preserving float<->uint map + warp redux ----------------
__device__ __forceinline__ uint32_t ordf(float f) {
    uint32_t u = __float_as_uint(f);
    return (u & 0x80000000u) ? ~u : (u | 0x80000000u);
}
__device__ __forceinline__ float unordf(uint32_t o) {
    uint32_t u = (o & 0x80000000u) ? (o ^ 0x80000000u) : ~o;
    return __uint_as_float(u);
}
__device__ __forceinline__ uint32_t redux_max(uint32_t v) {
    uint32_t r;
    asm("redux.sync.max.u32 %0, %1, 0xffffffff;" : "=r"(r) : "r"(v));
    return r;
}
__device__ __forceinline__ uint32_t redux_min(uint32_t v) {
    uint32_t r;
    asm("redux.sync.min.u32 %0, %1, 0xffffffff;" : "=r"(r) : "r"(v));
    return r;
}
__device__ __forceinline__ void warp_top2(float& M, float& M2, int& I) {
    const uint32_t mo  = ordf(M);
    const uint32_t Mo  = redux_max(mo);
    const uint32_t c2  = (mo == Mo) ? ordf(M2) : mo;
    const uint32_t M2o = redux_max(c2);
    const uint32_t ic  = (mo == Mo) ? (uint32_t)I : 0x7FFFFFFFu;
    I  = (int)redux_min(ic);
    M  = unordf(Mo);
    M2 = unordf(M2o);
}

// ---------------- PTX helpers --------------------------------------------------
__device__ __forceinline__ uint32_t smem_u32(const void* p) {
    uint32_t a;
    asm("{ .reg .u64 t; cvta.to.shared.u64 t, %1; cvt.u32.u64 %0, t; }"
        : "=r"(a) : "l"(p));
    return a;
}
#define LDMATRIX_X4(r0, r1, r2, r3, addr) \
    asm volatile("ldmatrix.sync.aligned.m8n8.x4.shared.b16 {%0,%1,%2,%3}, [%4];" \
                 : "=r"(r0), "=r"(r1), "=r"(r2), "=r"(r3) : "r"(addr))
#define MMA16816(d, a, b0, b1) \
    asm volatile("mma.sync.aligned.m16n8k16.row.col.f32.bf16.bf16.f32 " \
                 "{%0,%1,%2,%3}, {%4,%5,%6,%7}, {%8,%9}, {%0,%1,%2,%3};" \
                 : "+f"((d)[0]), "+f"((d)[1]), "+f"((d)[2]), "+f"((d)[3]) \
                 : "r"((a)[0]), "r"((a)[1]), "r"((a)[2]), "r"((a)[3]), \
                   "r"(b0), "r"(b1))
#define CP_ASYNC16(dst, src) \
    asm volatile("cp.async.cg.shared.global [%0], [%1], 16;" \
                 :: "r"(dst), "l"(src) : "memory")
#define CP_COMMIT() asm volatile("cp.async.commit_group;" ::: "memory")
#define CP_WAIT0()  asm volatile("cp.async.wait_group 0;" ::: "memory")

// smem: A[buf]: 64 rows x 80B = 5120; B[buf]: 320 rows x 80B = 25600
#define A_OFF(buf) ((buf) * 5120)
#define B_OFF(buf) (10240 + (buf) * 25600)
#define GEMM_SMEM 61440

__device__ __forceinline__ uint32_t pkbf(float a, float b) {
    return (uint32_t)__bfloat16_as_ushort(__float2bfloat16_rn(a)) |
           ((uint32_t)__bfloat16_as_ushort(__float2bfloat16_rn(b)) << 16);
}

// ---------------- W^T split + accumulator zeroing (merged) -----------------------
__global__ __launch_bounds__(256)
void wsplit_kernel(const float* __restrict__ W) {
    __shared__ float tile[32][33];
    // block (0,0) also zeroes the global accumulators (runs before gemm/epilogue)
    if (blockIdx.x == 0 && blockIdx.y == 0) {
        for (int i = threadIdx.x; i < GK; i += 256) { g_prob[i] = 0.0f; g_cnt[i] = 0; }
        if (threadIdx.x == 0) g_fix_cnt = 0;
    }
    const int n0 = blockIdx.x * 32;
    const int k0 = blockIdx.y * 32;
    const int tx = threadIdx.x & 31;
    const int ty = threadIdx.x >> 5;
#pragma unroll
    for (int i = 0; i < 32; i += 8)
        tile[ty + i][tx] = W[(size_t)(k0 + ty + i) * GK + n0 + tx];
    __syncthreads();
#pragma unroll
    for (int i = 0; i < 32; i += 8) {
        const int n = n0 + ty + i, k = k0 + tx;
        float x = tile[tx][ty + i];
        g_wth[(size_t)n * DD + k] = __float2bfloat16_rn(x);
        g_wtf[(size_t)n * DD + k] = x;
    }
}

// ---------------- HMMA GEMM: 256 threads, CTA tile 64x320, 2 CTAs/SM (R8/R15) ----
__global__ __launch_bounds__(256, 2)
void gemm_hmma_kernel(const float* __restrict__ X, const float* __restrict__ bias) {
    extern __shared__ char sm[];
    const uint32_t smb = smem_u32(sm);
    const int tid  = threadIdx.x;
    const int lane = tid & 31;
    const int wid  = tid >> 5;
    const int wm   = wid & 1;
    const int wn   = wid >> 1;
    const int g    = blockIdx.x;
    const int bm   = blockIdx.y;

    float acc[2][10][4];
#pragma unroll
    for (int i = 0; i < 2; i++)
#pragma unroll
        for (int j = 0; j < 10; j++)
#pragma unroll
            for (int q = 0; q < 4; q++) acc[i][j][q] = 0.0f;

    const int a_row = tid >> 2;
    const int a_q   = tid & 3;
    const float* Xrow = X + (size_t)(bm * 64 + a_row) * DD + a_q * 8;

    for (int idx = tid; idx < 1280; idx += 256) {
        int n = idx >> 2, c = idx & 3;
        CP_ASYNC16(smb + B_OFF(0) + n * 80 + c * 16,
                   &g_wth[(size_t)(g * KC + n) * DD + c * 8]);
    }
    CP_COMMIT();
    {
        float4 v0 = *(const float4*)(Xrow);
        float4 v1 = *(const float4*)(Xrow + 4);
        uint4 pk = make_uint4(pkbf(v0.x, v0.y), pkbf(v0.z, v0.w),
                              pkbf(v1.x, v1.y), pkbf(v1.z, v1.w));
        *(uint4*)(sm + A_OFF(0) + a_row * 80 + a_q * 16) = pk;
    }
    CP_WAIT0();
    __syncthreads();

    const int a_lrow = (lane & 15);
    const int a_lcol = (lane >> 4) * 16;
    const int b_lrow = (lane & 7) + ((lane >> 4) & 1) * 8;
    const int b_lcol = ((lane >> 3) & 1) * 16;
    const int b_nbase = (wn * 80 + b_lrow) * 80 + b_lcol;

    int buf = 0;
    for (int t = 0; t < NITER; t++) {
        float4 nv0, nv1;
        if (t + 1 < NITER) {
            nv0 = *(const float4*)(Xrow + (t + 1) * 32);
            nv1 = *(const float4*)(Xrow + (t + 1) * 32 + 4);
            const int k0 = (t + 1) * 32;
            for (int idx = tid; idx < 1280; idx += 256) {
                int n = idx >> 2, c = idx & 3;
                CP_ASYNC16(smb + B_OFF(buf ^ 1) + n * 80 + c * 16,
                           &g_wth[(size_t)(g * KC + n) * DD + k0 + c * 8]);
            }
            CP_COMMIT();
        }
#pragma unroll
        for (int kh = 0; kh < 2; kh++) {
            uint32_t ah[2][4];
#pragma unroll
            for (int mt = 0; mt < 2; mt++) {
                const int row = wm * 32 + mt * 16 + a_lrow;
                LDMATRIX_X4(ah[mt][0], ah[mt][1], ah[mt][2], ah[mt][3],
                            smb + A_OFF(buf) + row * 80 + kh * 32 + a_lcol);
            }
            uint32_t bb[2][4];
            LDMATRIX_X4(bb[0][0], bb[0][1], bb[0][2], bb[0][3],
                        smb + B_OFF(buf) + b_nbase + kh * 32);
#pragma unroll
            for (int bg = 0; bg < 5; bg++) {
                const int cur = bg & 1, nxt = cur ^ 1;
                if (bg < 4)
                    LDMATRIX_X4(bb[nxt][0], bb[nxt][1], bb[nxt][2], bb[nxt][3],
                                smb + B_OFF(buf) + b_nbase + (bg + 1) * 16 * 80 + kh * 32);
#pragma unroll
                for (int h2 = 0; h2 < 2; h2++) {
                    MMA16816(acc[0][bg * 2 + h2], ah[0], bb[cur][h2 * 2], bb[cur][h2 * 2 + 1]);
                    MMA16816(acc[1][bg * 2 + h2], ah[1], bb[cur][h2 * 2], bb[cur][h2 * 2 + 1]);
                }
            }
        }
        if (t + 1 < NITER) {
            uint4 pk = make_uint4(pkbf(nv0.x, nv0.y), pkbf(nv0.z, nv0.w),
                                  pkbf(nv1.x, nv1.y), pkbf(nv1.z, nv1.w));
            *(uint4*)(sm + A_OFF(buf ^ 1) + a_row * 80 + a_q * 16) = pk;
            CP_WAIT0();
        }
        __syncthreads();
        buf ^= 1;
    }

#pragma unroll
    for (int nt = 0; nt < 10; nt++) {
        const int c = wn * 80 + nt * 8 + (lane & 3) * 2;
        const float b0 = bias[g * KC + c];
        const float b1 = bias[g * KC + c + 1];
#pragma unroll
        for (int mt = 0; mt < 2; mt++) {
            const int r0 = bm * 64 + wm * 32 + mt * 16 + (lane >> 2);
            float* p0 = g_logits + ((size_t)r0 * 2 + g) * KC + c;
            float* p1 = g_logits + ((size_t)(r0 + 8) * 2 + g) * KC + c;
            *(float2*)p0 = make_float2(acc[mt][nt][0] + b0, acc[mt][nt][1] + b1);
            *(float2*)p1 = make_float2(acc[mt][nt][2] + b0, acc[mt][nt][3] + b1);
        }
    }
}

// ---------------- fused epilogue (R15 + same-group warp mapping) -------------------
__global__ __launch_bounds__(256)
void epilogue_kernel(const float* __restrict__ noise,
                     const float* __restrict__ cb,
                     float* __restrict__ out) {
    __shared__ float s_prob[GK];
    __shared__ int   s_cnt[GK];
    const int tid = threadIdx.x;
    for (int i = tid; i < GK; i += 256) { s_prob[i] = 0.0f; s_cnt[i] = 0; }
    __syncthreads();

    const int lane = tid & 31;
    const int warp = tid >> 5;
    const int wg   = blockIdx.x * 8 + warp;   // 0..4095
    const int g    = wg & 1;
    const int row0 = (wg >> 1) * 16;

    float pacc[10];
#pragma unroll
    for (int j = 0; j < 10; j++) pacc[j] = 0.0f;

    for (int pp = 0; pp < 16; pp++) {
        const int r = row0 + pp;
        const int pair = r * 2 + g;
        const float* lrow = g_logits + (size_t)pair * KC;
        const float* nrow = noise    + (size_t)pair * KC;

        // prefetch logits AND noise unconditionally (coalesced, MLP=20)
        float l[10], nv[10];
#pragma unroll
        for (int j = 0; j < 10; j++) {
            const int k = lane + 32 * j;
            l[j]  = lrow[k];
            nv[j] = nrow[k];
        }

        // hard top-2: local scan, then 3-op redux reduction
        float M = l[0], M2 = -3.4e38f; int I = lane;
#pragma unroll
        for (int j = 1; j < 10; j++) {
            if (l[j] > M) { M2 = M; M = l[j]; I = lane + 32 * j; }
            else if (l[j] > M2) M2 = l[j];
        }
        warp_top2(M, M2, I);

        // gumbel top-2: fgum computed only where the bound allows a win
        const float cut = M - GTH;
        float GM = -3.4e38f, GM2 = -3.4e38f; int GI = 0x7FFFFFFF;
#pragma unroll
        for (int j = 0; j < 10; j++) {
            if (l[j] > cut) {
                const float gl = l[j] + fgum(nv[j]);
                if (gl > GM)       { GM2 = GM; GM = gl; GI = lane + 32 * j; }
                else if (gl > GM2) { GM2 = gl; }
            }
        }
        warp_top2(GM, GM2, GI);

        // softmax accumulation (MUFU exp)
        float e[10];
        float s = 0.0f;
#pragma unroll
        for (int j = 0; j < 10; j++) { e[j] = __expf(l[j] - M); s += e[j]; }
#pragma unroll
        for (int off = 16; off; off >>= 1)
            s += __shfl_xor_sync(0xffffffffu, s, off);
        const float inv = 1.0f / s;
#pragma unroll
        for (int j = 0; j < 10; j++) pacc[j] += e[j] * inv;

        if (lane == 0) {
            atomicAdd(&s_cnt[g * KC + I], 1);
            if (M - M2 < THETA || GM - GM2 < THETA) {
                int pos = atomicAdd(&g_fix_cnt, 1);
                if (pos < MAXFIX) g_fix[pos] = make_int2(pair, I);
            }
        }

        const float4* src = (const float4*)(cb + ((size_t)(g * KC) + GI) * VDIM);
        float4*       dst = (float4*)(out + (size_t)r * 256 + g * VDIM);
        dst[lane] = src[lane];
    }

#pragma unroll
    for (int j = 0; j < 10; j++)
        atomicAdd(&s_prob[g * KC + lane + 32 * j], pacc[j]);

    __syncthreads();
    for (int i = tid; i < GK; i += 256) {
        atomicAdd(&g_prob[i], s_prob[i]);
        atomicAdd(&g_cnt[i],  s_cnt[i]);
    }
}

// ---------------- fixup: exact resolve of candidates (R15 verbatim) ----------------
__global__ __launch_bounds__(256)
void fixup_kernel(const float* __restrict__ X, const float* __restrict__ bias,
                  const float* __restrict__ noise, const float* __restrict__ cb,
                  float* __restrict__ out) {
    __shared__ int s_cols[8][32];
    __shared__ int s_n[8];
    const int lane = threadIdx.x & 31;
    const int w    = threadIdx.x >> 5;
    const int gw   = blockIdx.x * 8 + w;
    const int nwarps = gridDim.x * 8;
    const int total = min(g_fix_cnt, MAXFIX);

    for (int f = gw; f < total; f += nwarps) {
        const int2 rec = g_fix[f];
        const int pair = rec.x, Iapp = rec.y;
        const int r = pair >> 1, g = pair & 1;
        const float* lrow = g_logits + (size_t)pair * KC;
        const float* nrow = noise    + (size_t)pair * KC;

        float l[10], nv[10];
#pragma unroll
        for (int j = 0; j < 10; j++) {
            const int k = lane + 32 * j;
            l[j]  = lrow[k];
            nv[j] = nrow[k];
        }

        float M = l[0];
#pragma unroll
        for (int j = 1; j < 10; j++) M = fmaxf(M, l[j]);
        M = unordf(redux_max(ordf(M)));

        const float cut = M - GTH;
        float gl[10];
        float GM = -3.4e38f;
#pragma unroll
        for (int j = 0; j < 10; j++) {
            gl[j] = -3.4e38f;
            if (l[j] > cut) {
                float u = fmaf(nv[j], 0.999998f, 1e-6f);
                gl[j] = l[j] - flog(-flog(u));
                GM = fmaxf(GM, gl[j]);
            }
        }
        GM = unordf(redux_max(ordf(GM)));

        if (lane == 0) s_n[w] = 0;
        __syncwarp();
#pragma unroll
        for (int j = 0; j < 10; j++) {
            const int hardc = l[j]  > M  - THETA;
            const int gumc  = gl[j] > GM - THETA;
            if (hardc || gumc) {
                int p = atomicAdd(&s_n[w], 1);
                if (p < 32)
                    s_cols[w][p] = (lane + 32 * j) | (hardc << 16) | (gumc << 17);
            }
        }
        __syncwarp();
        const int cnt = min(s_n[w], 32);

        float le = -3.4e38f, ge = -3.4e38f;
        int ci = KC;
        if (lane < cnt) {
            const int ent = s_cols[w][lane];
            ci = ent & 0xFFFF;
            const float* xr = X + (size_t)r * DD;
            const float* wc = g_wtf + (size_t)(g * KC + ci) * DD;
            float acc = 0.0f;
            for (int k = 0; k < DD; k++)
                acc = fmaf(xr[k], wc[k], acc);       // ascending-k exact chain
            const float ex = acc + bias[g * KC + ci];
            float u = fmaf(nrow[ci], 0.999998f, 1e-6f);
            const float gum = -flog(-flog(u));
            if (ent & 0x10000) le = ex;
            if (ent & 0x20000) ge = ex + gum;
        }
        int hi = ci, gi = ci;
        float hv = le, gv = ge;
#pragma unroll
        for (int off = 16; off; off >>= 1) {
            float ov = __shfl_xor_sync(0xffffffffu, hv, off);
            int   oi = __shfl_xor_sync(0xffffffffu, hi, off);
            if (ov > hv || (ov == hv && oi < hi)) { hv = ov; hi = oi; }
            float o2 = __shfl_xor_sync(0xffffffffu, gv, off);
            int   i2 = __shfl_xor_sync(0xffffffffu, gi, off);
            if (o2 > gv || (o2 == gv && i2 < gi)) { gv = o2; gi = i2; }
        }

        if (lane == 0 && hi != Iapp) {
            atomicSub(&g_cnt[g * KC + Iapp], 1);
            atomicAdd(&g_cnt[g * KC + hi], 1);
        }
        const float4* src = (const float4*)(cb + ((size_t)(g * KC) + gi) * VDIM);
        float4*       dst = (float4*)(out + (size_t)r * 256 + g * VDIM);
        dst[lane] = src[lane];
        __syncwarp();
    }
}

// ---------------- perplexity scalars (parallel reduction) ---------------------------
__global__ void finalize_kernel(float* __restrict__ out, int scalar_base) {
    __shared__ float sh[GK], sp[GK];
    __shared__ float red[4];
    const int t = threadIdx.x;
    if (t < GK) {
        float hp = (float)g_cnt[t] * (1.0f / (float)BT);
        float ap = g_prob[t]       * (1.0f / (float)BT);
        sh[t] = hp * logf(hp + 1e-7f);
        sp[t] = ap * logf(ap + 1e-7f);
    }
    __syncthreads();
    if (t < 64) {
        const int gi = t >> 5, lane = t & 31;
        float a = 0.0f, b = 0.0f;
        for (int k = lane; k < KC; k += 32) {
            a += sh[gi * KC + k];
            b += sp[gi * KC + k];
        }
#pragma unroll
        for (int off = 16; off; off >>= 1) {
            a += __shfl_xor_sync(0xffffffffu, a, off);
            b += __shfl_xor_sync(0xffffffffu, b, off);
        }
        if (lane == 0) { red[gi] = a; red[2 + gi] = b; }
    }
    __syncthreads();
    if (t == 0) {
        out[scalar_base]     = expf(-red[0]) + expf(-red[1]);
        out[scalar_base + 1] = expf(-red[2]) + expf(-red[3]);
    }
}

// ---------------- launch --------------------------------------------------------------
extern "C" void kernel_launch(void* const* d_in, const int* in_sizes, int n_in,
                              void* d_out, int out_size) {
    const float* x     = (const float*)d_in[0];
    const float* W     = (const float*)d_in[1];
    const float* bias  = (const float*)d_in[2];
    const float* cb    = (const float*)d_in[3];
    const float* noise = (const float*)d_in[4];
    float* out = (float*)d_out;

    cudaFuncSetAttribute(gemm_hmma_kernel,
                         cudaFuncAttributeMaxDynamicSharedMemorySize, GEMM_SMEM);

    dim3 wgrid(20, 24);
    wsplit_kernel<<<wgrid, 256>>>(W);   // also zeroes accumulators (block 0,0)
    dim3 grid(2, 512);
    gemm_hmma_kernel<<<grid, 256, GEMM_SMEM>>>(x, bias);
    epilogue_kernel<<<512, 256>>>(noise, cb, out);
    fixup_kernel<<<512, 256>>>(x, bias, noise, cb, out);
    finalize_kernel<<<1, GK>>>(out, out_size - 2);
}